// round 1
// baseline (speedup 1.0000x reference)
#include <cuda_runtime.h>
#include <cstdint>
#include <cstddef>

// Bihomogeneous_k3: N=5 vars, degree-3 monomials (35), pairwise p<=q products
// (630 re) + strict p<q (595 im) = 1225 fp32 outputs per batch row.
// HBM-write-bound kernel: one warp per row, monomials staged in smem,
// coalesced streaming stores.

#define NVAR 5
#define M3 35
#define NPAIR 630
#define NCOL 1225
#define WARPS_PER_BLOCK 8

struct Tab {
    unsigned short pq[NCOL + 7];   // p | q<<6 | is_im<<12  (padded)
    unsigned short ijk[M3 + 5];    // i | j<<4 | k<<8       (padded)
};

static constexpr Tab make_tab() {
    Tab t{};
    // monomial index table: (i,j,k) with i<=j<=k
    int m = 0;
    for (int i = 0; i < NVAR; i++)
        for (int j = i; j < NVAR; j++)
            for (int k = j; k < NVAR; k++) {
                t.ijk[m] = (unsigned short)(i | (j << 4) | (k << 8));
                m++;
            }
    // pair table: first 630 columns = re of (p,q) p<=q in enumeration order
    int P[NPAIR] = {}, Q[NPAIR] = {};
    int c = 0;
    for (int p = 0; p < M3; p++)
        for (int q = p; q < M3; q++) { P[c] = p; Q[c] = q; c++; }
    for (int c2 = 0; c2 < NPAIR; c2++)
        t.pq[c2] = (unsigned short)(P[c2] | (Q[c2] << 6));
    // next 595 columns = im of strict pairs p<q, same enumeration order
    int ci = NPAIR;
    for (int c2 = 0; c2 < NPAIR; c2++)
        if (P[c2] < Q[c2])
            t.pq[ci++] = (unsigned short)(P[c2] | (Q[c2] << 6) | (1 << 12));
    return t;
}

__device__ const Tab g_tab = make_tab();

__global__ void __launch_bounds__(WARPS_PER_BLOCK * 32)
bihom_k3_kernel(const float* __restrict__ z_re,
                const float* __restrict__ z_im,
                float* __restrict__ out, int B)
{
    const int warp = threadIdx.x >> 5;
    const int lane = threadIdx.x & 31;
    const int row  = blockIdx.x * WARPS_PER_BLOCK + warp;

    __shared__ float2 szz[WARPS_PER_BLOCK][M3 + 1];
    __shared__ float  sz[WARPS_PER_BLOCK][2][NVAR + 3];

    if (row >= B) return;   // whole warp exits together (one row per warp)

    // stage 0: load this row's 5 complex inputs into smem (dynamic-index safe)
    if (lane < NVAR) {
        sz[warp][0][lane] = z_re[row * NVAR + lane];
        sz[warp][1][lane] = z_im[row * NVAR + lane];
    }
    __syncwarp();

    // stage 1: 35 complex monomials z_i * z_j * z_k
    for (int mm = lane; mm < M3; mm += 32) {
        const unsigned v = g_tab.ijk[mm];
        const int i = v & 15, j = (v >> 4) & 15, k = (v >> 8) & 15;
        const float ar = sz[warp][0][i], ai = sz[warp][1][i];
        const float br = sz[warp][0][j], bi = sz[warp][1][j];
        const float cr = sz[warp][0][k], ci = sz[warp][1][k];
        const float tr = ar * br - ai * bi;
        const float ti = ar * bi + ai * br;
        szz[warp][mm] = make_float2(tr * cr - ti * ci, tr * ci + ti * cr);
    }
    __syncwarp();

    // stage 2: 1225 outputs. zz_p * conj(zz_q):
    //   re = ap.x*aq.x + ap.y*aq.y ; im = ap.y*aq.x - ap.x*aq.y
    float* __restrict__ orow = out + (size_t)row * NCOL;
    const float2* zz = szz[warp];

    #pragma unroll 4
    for (int c = lane; c < NCOL; c += 32) {
        const unsigned v = g_tab.pq[c];
        const float2 a = zz[v & 63];         // broadcast-friendly (p nearly const per group)
        const float2 b = zz[(v >> 6) & 63];  // consecutive q -> conflict-free
        const float r = (v & 4096u) ? (a.y * b.x - a.x * b.y)
                                    : (a.x * b.x + a.y * b.y);
        __stcs(orow + c, r);                 // streaming store: write-once output
    }
}

extern "C" void kernel_launch(void* const* d_in, const int* in_sizes, int n_in,
                              void* d_out, int out_size) {
    const float* z_re = (const float*)d_in[0];
    const float* z_im = (const float*)d_in[1];
    float* out = (float*)d_out;
    const int B = in_sizes[0] / NVAR;
    const int grid = (B + WARPS_PER_BLOCK - 1) / WARPS_PER_BLOCK;
    bihom_k3_kernel<<<grid, WARPS_PER_BLOCK * 32>>>(z_re, z_im, out, B);
}